// round 4
// baseline (speedup 1.0000x reference)
#include <cuda_runtime.h>
#include <cuda_bf16.h>

// DiracScheduler: fft_convolve(events, upsampled one-hot(argmax(pos))) ==
// per-row right-shift of events by d_e = argmax_e * 128, zero-filled head.
//
// pos:    [1, 64, 1024]   float32   (d_in[0])
// events: [2, 64, 131072] float32   (d_in[1])
// out:    [2, 64, 131072] float32

#define N_EVENTS   64
#define START_SIZE 1024
#define N_SAMPLES  131072
#define UPFACTOR   (N_SAMPLES / START_SIZE)   // 128
#define BATCH      2
#define ROW_F4     (N_SAMPLES / 4)            // 32768 float4 per row

__device__ int g_delay[N_EVENTS];

// ---------------------------------------------------------------------------
// Kernel 1: per-event argmax over 1024 positions -> delay = idx * 128.
// One block per event, 256 threads, first-occurrence tie-break (jnp.argmax).
// ---------------------------------------------------------------------------
__global__ void argmax_kernel(const float* __restrict__ pos) {
    __shared__ float s_val[256];
    __shared__ int   s_idx[256];

    const int e   = blockIdx.x;
    const int tid = threadIdx.x;
    const float* p = pos + e * START_SIZE;

    float best = -3.402823466e+38f;
    int   bidx = 0;
    #pragma unroll
    for (int i = 0; i < START_SIZE / 256; ++i) {
        int idx = tid + i * 256;              // ascending idx per thread
        float v = p[idx];
        if (v > best) { best = v; bidx = idx; }
    }
    s_val[tid] = best;
    s_idx[tid] = bidx;
    __syncthreads();

    #pragma unroll
    for (int s = 128; s > 0; s >>= 1) {
        if (tid < s) {
            float ov = s_val[tid + s];
            int   oi = s_idx[tid + s];
            if (ov > s_val[tid] || (ov == s_val[tid] && oi < s_idx[tid])) {
                s_val[tid] = ov;
                s_idx[tid] = oi;
            }
        }
        __syncthreads();
    }
    if (tid == 0) g_delay[e] = s_idx[0] * UPFACTOR;
}

// ---------------------------------------------------------------------------
// Kernel 2: shifted copy. Delay is a multiple of 128 floats (=32 float4),
// so float4 alignment is preserved; loads and stores stay coalesced.
// grid = (ROW_F4/256, BATCH*N_EVENTS), block = 256.
// ---------------------------------------------------------------------------
__global__ void shift_kernel(const float4* __restrict__ ev,
                             float4* __restrict__ out) {
    const int row = blockIdx.y;               // b*64 + e
    const int e   = row & (N_EVENTS - 1);
    const int d4  = g_delay[e] >> 2;          // delay in float4 units

    const int t4 = blockIdx.x * blockDim.x + threadIdx.x;
    const long base = (long)row * ROW_F4;

    float4 v;
    if (t4 >= d4) {
        v = ev[base + t4 - d4];
    } else {
        v = make_float4(0.f, 0.f, 0.f, 0.f);
    }
    out[base + t4] = v;
}

extern "C" void kernel_launch(void* const* d_in, const int* in_sizes, int n_in,
                              void* d_out, int out_size) {
    const float* pos    = (const float*)d_in[0];
    const float4* ev    = (const float4*)d_in[1];
    float4* out         = (float4*)d_out;

    argmax_kernel<<<N_EVENTS, 256>>>(pos);

    dim3 grid(ROW_F4 / 256, BATCH * N_EVENTS);
    shift_kernel<<<grid, 256>>>(ev, out);
}